// round 13
// baseline (speedup 1.0000x reference)
#include <cuda_runtime.h>
#include <cstdint>

#define Sn 2
#define Bn 16
#define Kn 128
#define Hd 128
#define Wd 128
#define HWn (Hd*Wd)

#define EPSf 1e-6f
#define MAXD 181.01933598375618f
#define MAXD2 32768.0f
#define MPD (MAXD + EPSf)

#define NTILE 2048              // 128 rows * 16 b
#define NC 48                   // C-tail workers: 16 C1 + 32 IoU

typedef unsigned long long ull;

// ---- device scratch ----
static __device__ float4 g_t1[Bn * Hd];                 // per (b,row)
static __device__ float  g_part2[Bn * Hd * Kn * 2];     // ((b*Hd+row)*Kn + slot)*2 + s
static __device__ float  g_minn[Sn * Bn * Kn];
static __device__ float  g_iou[Sn * Bn];
static __device__ int    g_msum[Bn];
static __device__ int    g_c1;                          // AB completion tickets
static __device__ int    g_c2;                          // C completion counter

__device__ __forceinline__ float sqrt_ap(float x) {
    float r; asm("sqrt.approx.f32 %0, %1;" : "=f"(r) : "f"(x)); return r;
}
__device__ __forceinline__ float rcp_ap(float x) {
    float r; asm("rcp.approx.f32 %0, %1;" : "=f"(r) : "f"(x)); return r;
}
__device__ __forceinline__ ull pk(float lo, float hi) {
    ull r; asm("mov.b64 %0, {%1, %2};" : "=l"(r) : "f"(lo), "f"(hi)); return r;
}
__device__ __forceinline__ void upk(float& lo, float& hi, ull v) {
    asm("mov.b64 {%0, %1}, %2;" : "=f"(lo), "=f"(hi) : "l"(v));
}
__device__ __forceinline__ ull mul2(ull a, ull b) {
    ull r; asm("mul.rn.f32x2 %0, %1, %2;" : "=l"(r) : "l"(a), "l"(b)); return r;
}
__device__ __forceinline__ ull fma2(ull a, ull b, ull c) {
    ull r; asm("fma.rn.f32x2 %0, %1, %2, %3;" : "=l"(r) : "l"(a), "l"(b), "l"(c)); return r;
}
__device__ __forceinline__ float smoothl(float l) {
    return (l < 0.2f) ? (2.5f * l * l) : (l - 0.1f);
}

// ============================================================================
// Single kernel: AB tiles + ticketed C tail + finalize.
// grid: (row=128, b=16), block: 128 threads
// ============================================================================
__global__ void __launch_bounds__(128) fused_kernel(
    const float* __restrict__ hm, const float* __restrict__ wh_map,
    const float* __restrict__ reg_map, const float* __restrict__ reg_gt,
    const float* __restrict__ wh_gt, const int* __restrict__ ind,
    const int* __restrict__ ctr, const int* __restrict__ mask,
    float* __restrict__ out, int out_size)
{
    const int row = blockIdx.x, b = blockIdx.y;
    const int tid = threadIdx.x;
    const int wid = tid >> 5, lid = tid & 31;

    __shared__ float4 spq[Wd];
    __shared__ float  spx[Kn], sdy2[Kn];
    __shared__ int    wcnt[4];
    __shared__ float  red[4][4];
    __shared__ ull    sseg[Kn][9];          // padded
    __shared__ int    sticket;

    const float fy = (float)row, fx = (float)tid;

    // ---------------- AB tile ----------------
    // sigmoid for this row's cells (both s)
    const int base = b * HWn + row * Wd + tid;
    float h0 = hm[base];
    float h1 = hm[Bn * HWn + base];
    float p0 = 1.0f / (1.0f + __expf(-h0));
    float p1 = 1.0f / (1.0f + __expf(-h1));
    p0 = fminf(fmaxf(p0, 1e-4f), 1.0f - 1e-4f);
    p1 = fminf(fmaxf(p1, 1e-4f), 1.0f - 1e-4f);
    spq[tid] = make_float4(p0, p1, MPD - p0 * MAXD, MPD - p1 * MAXD);

    // compaction of valid points (thread = k)
    const int mk = mask[b * Kn + tid];
    unsigned bal = __ballot_sync(0xFFFFFFFFu, mk != 0);
    if (lid == 0) wcnt[wid] = __popc(bal);
    __syncthreads();
    int off = 0;
#pragma unroll
    for (int i = 0; i < 4; i++) if (i < wid) off += wcnt[i];
    const int V = wcnt[0] + wcnt[1] + wcnt[2] + wcnt[3];
    if (mk) {
        int slot = off + __popc(bal & ((1u << lid) - 1u));
        float pxk = (float)ctr[(b * Kn + tid) * 2 + 0];
        float pyk = (float)ctr[(b * Kn + tid) * 2 + 1];
        spx[slot] = pxk;
        float dyv = fy - pyk;
        sdy2[slot] = dyv * dyv;
    }
    __syncthreads();

    // term1: dmin per cell + row reduce
    float mind = MAXD2;
#pragma unroll 4
    for (int j = 0; j < V; j++) {
        float dxv = fx - spx[j];
        mind = fminf(mind, fmaf(dxv, dxv, sdy2[j]));
    }
    float dmin = sqrt_ap(mind);

    float v0 = p0 * dmin, v1 = p1 * dmin, v2 = p0, v3 = p1;
#pragma unroll
    for (int o = 16; o > 0; o >>= 1) {
        v0 += __shfl_down_sync(0xFFFFFFFFu, v0, o);
        v1 += __shfl_down_sync(0xFFFFFFFFu, v1, o);
        v2 += __shfl_down_sync(0xFFFFFFFFu, v2, o);
        v3 += __shfl_down_sync(0xFFFFFFFFu, v3, o);
    }
    if (lid == 0) { red[wid][0] = v0; red[wid][1] = v1; red[wid][2] = v2; red[wid][3] = v3; }
    __syncthreads();
    if (tid == 0) {
        float4 o4;
        o4.x = red[0][0] + red[1][0] + red[2][0] + red[3][0];
        o4.y = red[0][1] + red[1][1] + red[2][1] + red[3][1];
        o4.z = red[0][2] + red[1][2] + red[2][2] + red[3][2];
        o4.w = red[0][3] + red[1][3] + red[2][3] + red[3][3];
        g_t1[b * Hd + row] = o4;
    }

    // term2: item = (slot, 16-cell segment), 8V items; per-cell rcp, packed pow
    for (int w = tid; w < 8 * V; w += 128) {
        const int seg = w / V;
        const int slot = w - seg * V;
        const float px = spx[slot];
        const float dy2 = sdy2[slot];
        const int xb = seg << 4;
        const float u0 = (float)xb - px;
        ull acc = 0ULL;
#pragma unroll
        for (int c = 0; c < 16; c++) {
            float t = u0 + (float)c;
            float dsq = fmaf(t, t, dy2);
            float d = sqrt_ap(dsq);
            float4 pq = spq[xb + c];                 // broadcast LDS.128
            ull xv = fma2(pk(pq.x, pq.y), pk(d, d), pk(pq.z, pq.w));  // {x0,x1}
            float x0, x1; upk(x0, x1, xv);
            float P = x0 * x1;
            float r = rcp_ap(P);
            ull iv = mul2(pk(x1, x0), pk(r, r));     // {1/x0, 1/x1}
            ull a = mul2(iv, iv);                    // i^2
            a = mul2(a, a);                          // i^4
            a = mul2(a, a);                          // i^8
            acc = fma2(a, iv, acc);                  // += i^9 = x^-9
        }
        sseg[slot][seg] = acc;
    }
    __syncthreads();

    // combine 8 segments per slot; coalesced float2 store
    if (tid < V) {
        float s0 = 0.0f, s1 = 0.0f;
#pragma unroll
        for (int seg = 0; seg < 8; seg++) {
            float a0, a1; upk(a0, a1, sseg[tid][seg]);
            s0 += a0; s1 += a1;
        }
        *(float2*)&g_part2[((b * Hd + row) * Kn + tid) * 2] = make_float2(s0, s1);
    }

    // ---------------- ticket ----------------
    __threadfence();
    __syncthreads();
    if (tid == 0) sticket = atomicAdd(&g_c1, 1);
    __syncthreads();
    const int ticket = sticket;
    if (ticket < NTILE - NC) return;

    // ---------------- C tail (last 48 blocks) ----------------
    if (tid == 0) {
        while (*(volatile int*)&g_c1 < NTILE) __nanosleep(32);
    }
    __syncthreads();
    __threadfence();

    const int r = ticket - (NTILE - NC);
    if (r < 16) {
        // ---- C1 for b = r: thread = slot, sum 128 rows (L2-hot, coalesced) ----
        const int cb = r;
        // V for cb
        int mkc = mask[cb * Kn + tid];
        unsigned balc = __ballot_sync(0xFFFFFFFFu, mkc != 0);
        if (lid == 0) wcnt[wid] = __popc(balc);
        __syncthreads();
        const int Vc = wcnt[0] + wcnt[1] + wcnt[2] + wcnt[3];

        const float2* bp = (const float2*)&g_part2[(cb * Hd * Kn + tid) * 2];
        float s0 = 0.0f, s1 = 0.0f;
#pragma unroll 8
        for (int rr = 0; rr < Hd; rr++) {
            float2 v = bp[rr * Kn];
            s0 += v.x; s1 += v.y;
        }
        float m0 = 0.0f, m1 = 0.0f;
        if (tid < Vc) {
            m0 = powf(s0 * (1.0f / (float)HWn), -1.0f / 9.0f);
            m1 = powf(s1 * (1.0f / (float)HWn), -1.0f / 9.0f);
        }
        g_minn[(0 * Bn + cb) * Kn + tid] = m0;
        g_minn[(1 * Bn + cb) * Kn + tid] = m1;
    } else {
        // ---- IoU for sb = r-16: thread = k ----
        const int sb = r - 16;
        const int cb = sb & (Bn - 1);
        const int k = tid;
        const int mki = mask[cb * Kn + k];
        unsigned bali = __ballot_sync(0xFFFFFFFFu, mki != 0);
        float v = 0.0f;
        if (mki) {
            int id = ind[cb * Kn + k];
            float R0 = reg_map[(sb * 2 + 0) * HWn + id];
            float R1 = reg_map[(sb * 2 + 1) * HWn + id];
            float W0 = wh_map[(sb * 2 + 0) * HWn + id];
            float W1 = wh_map[(sb * 2 + 1) * HWn + id];
            float g0 = reg_gt[(cb * Kn + k) * 2 + 0];
            float g1 = reg_gt[(cb * Kn + k) * 2 + 1];
            float wg = wh_gt[(cb * Kn + k) * 2 + 0];
            float hg = wh_gt[(cb * Kn + k) * 2 + 1];
            float adx = fabsf(g0 - R0);
            float ady = fabsf(g1 - R1);
            float ldx = 1.0f - fmaxf((wg - 2.0f * adx) / (wg + 2.0f * adx + EPSf), 0.0f);
            float ldy = 1.0f - fmaxf((hg - 2.0f * ady) / (hg + 2.0f * ady + EPSf), 0.0f);
            float ldw = 1.0f - fminf(wg / (W0 + EPSf), W0 / (wg + EPSf));
            float ldh = 1.0f - fminf(hg / (W1 + EPSf), W1 / (hg + EPSf));
            v = smoothl(ldx) + smoothl(ldy) + smoothl(ldw) + smoothl(ldh);
        }
#pragma unroll
        for (int o = 16; o > 0; o >>= 1) v += __shfl_down_sync(0xFFFFFFFFu, v, o);
        if (lid == 0) { red[wid][0] = v; wcnt[wid] = __popc(bali); }
        __syncthreads();
        if (tid == 0) {
            g_iou[sb] = red[0][0] + red[1][0] + red[2][0] + red[3][0];
            if (sb < Bn) g_msum[sb] = wcnt[0] + wcnt[1] + wcnt[2] + wcnt[3];
        }
    }

    // ---- completion + finalize ----
    __threadfence();
    __syncthreads();
    if (tid == 0) {
        int prev = atomicAdd(&g_c2, 1);
        sticket = (prev == NC - 1) ? 1 : 0;
    }
    __syncthreads();

    if (sticket) {
        __threadfence();
        __shared__ float sterm_hm[Sn * Bn], sterm_iou[Sn * Bn];
        // 4 warps, sb strided by 4
        for (int sb2 = wid; sb2 < Sn * Bn; sb2 += 4) {
            const int cb = sb2 & (Bn - 1);
            const int s = sb2 >> 4;
            float t2s = 0.0f, num = 0.0f, den = 0.0f;
#pragma unroll
            for (int t = 0; t < 4; t++) {
                t2s += g_minn[sb2 * Kn + lid + t * 32];
                float4 v = g_t1[cb * Hd + lid + t * 32];
                num += (s == 0) ? v.x : v.y;
                den += (s == 0) ? v.z : v.w;
            }
#pragma unroll
            for (int o = 16; o > 0; o >>= 1) {
                t2s += __shfl_down_sync(0xFFFFFFFFu, t2s, o);
                num += __shfl_down_sync(0xFFFFFFFFu, num, o);
                den += __shfl_down_sync(0xFFFFFFFFu, den, o);
            }
            if (lid == 0) {
                int ms = g_msum[cb];
                float validb = (ms > 0) ? 1.0f : 0.0f;
                float fm = fmaxf((float)ms, 1.0f);
                float t1 = num / (den + EPSf);
                sterm_hm[sb2] = (t1 + t2s / fm) * validb;
                sterm_iou[sb2] = (g_iou[sb2] / (fm * 4.0f)) * validb;
            }
        }
        __syncthreads();
        if (tid == 0) {
            float hm_loss = 0.0f, iou_loss = 0.0f;
            for (int i = 0; i < Sn * Bn; i++) { hm_loss += sterm_hm[i]; iou_loss += sterm_iou[i]; }
            hm_loss *= (1.0f / (float)(Sn * Bn));
            iou_loss *= (1.0f / (float)(Sn * Bn));
            float loss = 1.0f * hm_loss + 0.1f * iou_loss;
            out[0] = loss;
            if (out_size > 1) out[1] = hm_loss;
            if (out_size > 2) out[2] = iou_loss;
            g_c1 = 0;                 // reset for next graph replay
            g_c2 = 0;                 // (all spinners already passed; safe)
        }
    }
}

// ============================================================================
extern "C" void kernel_launch(void* const* d_in, const int* in_sizes, int n_in,
                              void* d_out, int out_size)
{
    const float* hm      = (const float*)d_in[0];
    const float* wh_map  = (const float*)d_in[1];
    const float* reg_map = (const float*)d_in[2];
    const float* reg_gt  = (const float*)d_in[3];
    const float* wh_gt   = (const float*)d_in[4];
    const int*   ind     = (const int*)d_in[5];
    const int*   ctr     = (const int*)d_in[6];
    const int*   mask    = (const int*)d_in[7];
    float* out = (float*)d_out;

    dim3 grid(Hd, Bn);
    fused_kernel<<<grid, 128>>>(hm, wh_map, reg_map, reg_gt, wh_gt,
                                ind, ctr, mask, out, out_size);
}

// round 14
// speedup vs baseline: 1.0504x; 1.0504x over previous
#include <cuda_runtime.h>
#include <cstdint>

#define Sn 2
#define Bn 16
#define Kn 128
#define Hd 128
#define Wd 128
#define HWn (Hd*Wd)

#define EPSf 1e-6f
#define MAXD 181.01933598375618f
#define MAXD2 32768.0f
#define MPD (MAXD + EPSf)

#define C1_BLOCKS 512
#define IOU_BLOCKS 32
#define TOT_BLOCKS (C1_BLOCKS + IOU_BLOCKS)

typedef unsigned long long ull;

// ---- device scratch ----
static __device__ float4 g_t1[Bn * Hd];                    // per (b,row)
static __device__ float  g_part2[Bn * Kn * 256 * 2];       // ((b*Kn+slot)*256 + rowhalf)*2 + s
static __device__ float  g_minn[Sn * Bn * Kn];
static __device__ float  g_iou[Sn * Bn];
static __device__ int    g_msum[Bn];
static __device__ int    g_done;

__device__ __forceinline__ float sqrt_ap(float x) {
    float r; asm("sqrt.approx.f32 %0, %1;" : "=f"(r) : "f"(x)); return r;
}
__device__ __forceinline__ float rcp_ap(float x) {
    float r; asm("rcp.approx.f32 %0, %1;" : "=f"(r) : "f"(x)); return r;
}
__device__ __forceinline__ ull pk(float lo, float hi) {
    ull r; asm("mov.b64 %0, {%1, %2};" : "=l"(r) : "f"(lo), "f"(hi)); return r;
}
__device__ __forceinline__ void upk(float& lo, float& hi, ull v) {
    asm("mov.b64 {%0, %1}, %2;" : "=f"(lo), "=f"(hi) : "l"(v));
}
__device__ __forceinline__ ull mul2(ull a, ull b) {
    ull r; asm("mul.rn.f32x2 %0, %1, %2;" : "=l"(r) : "l"(a), "l"(b)); return r;
}
__device__ __forceinline__ ull fma2(ull a, ull b, ull c) {
    ull r; asm("fma.rn.f32x2 %0, %1, %2, %3;" : "=l"(r) : "l"(a), "l"(b), "l"(c)); return r;
}
__device__ __forceinline__ float smoothl(float l) {
    return (l < 0.2f) ? (2.5f * l * l) : (l - 0.1f);
}

// ============================================================================
// Kernel 1 — fused pass AB: sigmoid + compaction; term1 (dmin) + term2 partials
// grid: (row=128, b=16), block: 128 threads
// ============================================================================
__global__ void __launch_bounds__(128) passAB_kernel(
    const float* __restrict__ hm, const int* __restrict__ ctr,
    const int* __restrict__ mask)
{
    const int row = blockIdx.x, b = blockIdx.y;
    const int tid = threadIdx.x;
    const int wid = tid >> 5, lid = tid & 31;

    __shared__ float4 spq[Wd];
    __shared__ float  spx[Kn], sdy2[Kn];
    __shared__ int    wcnt[4];
    __shared__ float  red[4][4];

    const float fy = (float)row, fx = (float)tid;

    // --- sigmoid for this row's cells (both s) ---
    const int base = b * HWn + row * Wd + tid;
    float h0 = hm[base];
    float h1 = hm[Bn * HWn + base];
    float p0 = 1.0f / (1.0f + __expf(-h0));
    float p1 = 1.0f / (1.0f + __expf(-h1));
    p0 = fminf(fmaxf(p0, 1e-4f), 1.0f - 1e-4f);
    p1 = fminf(fmaxf(p1, 1e-4f), 1.0f - 1e-4f);
    spq[tid] = make_float4(p0, p1, MPD - p0 * MAXD, MPD - p1 * MAXD);

    // --- compaction of valid points (thread = k) ---
    const int mk = mask[b * Kn + tid];
    unsigned bal = __ballot_sync(0xFFFFFFFFu, mk != 0);
    if (lid == 0) wcnt[wid] = __popc(bal);
    __syncthreads();
    int off = 0;
#pragma unroll
    for (int i = 0; i < 4; i++) if (i < wid) off += wcnt[i];
    const int V = wcnt[0] + wcnt[1] + wcnt[2] + wcnt[3];
    if (mk) {
        int slot = off + __popc(bal & ((1u << lid) - 1u));
        float pxk = (float)ctr[(b * Kn + tid) * 2 + 0];
        float pyk = (float)ctr[(b * Kn + tid) * 2 + 1];
        spx[slot] = pxk;
        float dyv = fy - pyk;
        sdy2[slot] = dyv * dyv;
    }
    __syncthreads();

    // ---- term1: dmin per cell + row reduce ----
    float mind = MAXD2;
#pragma unroll 4
    for (int j = 0; j < V; j++) {
        float dxv = fx - spx[j];
        mind = fminf(mind, fmaf(dxv, dxv, sdy2[j]));
    }
    float dmin = sqrt_ap(mind);

    float v0 = p0 * dmin, v1 = p1 * dmin, v2 = p0, v3 = p1;
#pragma unroll
    for (int o = 16; o > 0; o >>= 1) {
        v0 += __shfl_down_sync(0xFFFFFFFFu, v0, o);
        v1 += __shfl_down_sync(0xFFFFFFFFu, v1, o);
        v2 += __shfl_down_sync(0xFFFFFFFFu, v2, o);
        v3 += __shfl_down_sync(0xFFFFFFFFu, v3, o);
    }
    if (lid == 0) { red[wid][0] = v0; red[wid][1] = v1; red[wid][2] = v2; red[wid][3] = v3; }
    __syncthreads();
    if (tid == 0) {
        float4 o4;
        o4.x = red[0][0] + red[1][0] + red[2][0] + red[3][0];
        o4.y = red[0][1] + red[1][1] + red[2][1] + red[3][1];
        o4.z = red[0][2] + red[1][2] + red[2][2] + red[3][2];
        o4.w = red[0][3] + red[1][3] + red[2][3] + red[3][3];
        g_t1[b * Hd + row] = o4;
    }

    // ---- term2: work item = (valid slot, half-row); per-cell rcp, min issues ----
    for (int w = tid; w < 2 * Kn; w += 128) {
        const int slot = w >> 1, half = w & 1;
        ull acc = 0ULL;
        if (slot < V) {
            const float px = spx[slot];
            const float dy2 = sdy2[slot];
            const int xb = half << 6;
            const float u0 = (float)xb - px;
#pragma unroll 8
            for (int c = 0; c < 64; c++) {
                float t = u0 + (float)c;
                float dsq = fmaf(t, t, dy2);
                float d = sqrt_ap(dsq);
                float4 pq = spq[xb + c];                  // broadcast LDS.128
                ull xv = fma2(pk(pq.x, pq.y), pk(d, d), pk(pq.z, pq.w));  // {x0,x1}
                float x0, x1; upk(x0, x1, xv);
                float P = x0 * x1;
                float r = rcp_ap(P);
                ull iv = mul2(pk(x1, x0), pk(r, r));      // {1/x0, 1/x1}
                ull a = mul2(iv, iv);                     // i^2
                a = mul2(a, a);                           // i^4
                a = mul2(a, a);                           // i^8
                acc = fma2(a, iv, acc);                   // += i^9 = x^-9
            }
        }
        float a0, a1; upk(a0, a1, acc);
        const int rr = row * 2 + half;
        *(float2*)&g_part2[((b * Kn + slot) * 256 + rr) * 2] = make_float2(a0, a1);
    }
}

// ============================================================================
// Kernel 2 — fused C1 reduction + IoU + (last block) finalize
// grid: 544 blocks x 256 threads
// ============================================================================
__global__ void __launch_bounds__(256) passC_kernel(
    const float* __restrict__ wh_map, const float* __restrict__ reg_map,
    const float* __restrict__ reg_gt, const float* __restrict__ wh_gt,
    const int* __restrict__ ind, const int* __restrict__ mask,
    float* __restrict__ out, int out_size)
{
    const int bid = blockIdx.x;
    const int tid = threadIdx.x;
    const int warpid = tid >> 5, lane = tid & 31;

    __shared__ int   wcnt[4];
    __shared__ float wred[4];
    __shared__ int   wv[4];
    __shared__ int   slast;

    if (bid < C1_BLOCKS) {
        // ---- C1: reduce over 256 row-halves ----
        const int sb = bid >> 4;                 // 0..31
        const int s = sb >> 4, b = sb & (Bn - 1);
        const int slot = ((bid & 15) << 3) + warpid;

        if (tid < Kn) {
            int mk = mask[b * Kn + tid];
            unsigned balm = __ballot_sync(0xFFFFFFFFu, mk != 0);
            if ((tid & 31) == 0) wcnt[tid >> 5] = __popc(balm);
        }
        __syncthreads();
        const int V = wcnt[0] + wcnt[1] + wcnt[2] + wcnt[3];

        float v = 0.0f;
        if (slot < V) {
            const float* bp = &g_part2[((b * Kn + slot) * 256) * 2 + s];
            float ssum = 0.0f;
#pragma unroll
            for (int t = 0; t < 8; t++) ssum += bp[(lane + t * 32) * 2];
#pragma unroll
            for (int o = 16; o > 0; o >>= 1) ssum += __shfl_down_sync(0xFFFFFFFFu, ssum, o);
            if (lane == 0)
                v = powf(ssum * (1.0f / (float)HWn), -1.0f / 9.0f);
        }
        if (lane == 0) g_minn[sb * Kn + slot] = v;
    } else {
        // ---- IoU: per (s,b), thread = k (first 128 threads) ----
        const int sb = bid - C1_BLOCKS;
        const int b = sb & (Bn - 1);
        if (tid < Kn) {
            const int k = tid;
            const int mk = mask[b * Kn + k];
            unsigned balm = __ballot_sync(0xFFFFFFFFu, mk != 0);
            float v = 0.0f;
            if (mk) {
                int id = ind[b * Kn + k];
                float R0 = reg_map[(sb * 2 + 0) * HWn + id];
                float R1 = reg_map[(sb * 2 + 1) * HWn + id];
                float W0 = wh_map[(sb * 2 + 0) * HWn + id];
                float W1 = wh_map[(sb * 2 + 1) * HWn + id];
                float g0 = reg_gt[(b * Kn + k) * 2 + 0];
                float g1 = reg_gt[(b * Kn + k) * 2 + 1];
                float wg = wh_gt[(b * Kn + k) * 2 + 0];
                float hg = wh_gt[(b * Kn + k) * 2 + 1];
                float adx = fabsf(g0 - R0);
                float ady = fabsf(g1 - R1);
                float ldx = 1.0f - fmaxf((wg - 2.0f * adx) / (wg + 2.0f * adx + EPSf), 0.0f);
                float ldy = 1.0f - fmaxf((hg - 2.0f * ady) / (hg + 2.0f * ady + EPSf), 0.0f);
                float ldw = 1.0f - fminf(wg / (W0 + EPSf), W0 / (wg + EPSf));
                float ldh = 1.0f - fminf(hg / (W1 + EPSf), W1 / (hg + EPSf));
                v = smoothl(ldx) + smoothl(ldy) + smoothl(ldw) + smoothl(ldh);
            }
#pragma unroll
            for (int o = 16; o > 0; o >>= 1) v += __shfl_down_sync(0xFFFFFFFFu, v, o);
            if ((tid & 31) == 0) { wred[tid >> 5] = v; wv[tid >> 5] = __popc(balm); }
        }
        __syncthreads();
        if (tid == 0) {
            g_iou[sb] = wred[0] + wred[1] + wred[2] + wred[3];
            if (sb < Bn) g_msum[sb] = wv[0] + wv[1] + wv[2] + wv[3];
        }
    }

    // ---- completion protocol ----
    __threadfence();
    __syncthreads();
    if (tid == 0) {
        int prev = atomicAdd(&g_done, 1);
        slast = (prev == TOT_BLOCKS - 1) ? 1 : 0;
        if (slast) g_done = 0;
    }
    __syncthreads();

    if (slast) {
        __threadfence();
        __shared__ float sterm_hm[Sn * Bn], sterm_iou[Sn * Bn];
        for (int sb2 = warpid; sb2 < Sn * Bn; sb2 += 8) {
            const int b = sb2 & (Bn - 1);
            const int s = sb2 >> 4;
            float t2s = 0.0f, num = 0.0f, den = 0.0f;
#pragma unroll
            for (int t = 0; t < 4; t++) {
                t2s += g_minn[sb2 * Kn + lane + t * 32];
                float4 v = g_t1[b * Hd + lane + t * 32];
                num += (s == 0) ? v.x : v.y;
                den += (s == 0) ? v.z : v.w;
            }
#pragma unroll
            for (int o = 16; o > 0; o >>= 1) {
                t2s += __shfl_down_sync(0xFFFFFFFFu, t2s, o);
                num += __shfl_down_sync(0xFFFFFFFFu, num, o);
                den += __shfl_down_sync(0xFFFFFFFFu, den, o);
            }
            if (lane == 0) {
                int ms = g_msum[b];
                float validb = (ms > 0) ? 1.0f : 0.0f;
                float fm = fmaxf((float)ms, 1.0f);
                float t1 = num / (den + EPSf);
                sterm_hm[sb2] = (t1 + t2s / fm) * validb;
                sterm_iou[sb2] = (g_iou[sb2] / (fm * 4.0f)) * validb;
            }
        }
        __syncthreads();
        if (tid == 0) {
            float hm_loss = 0.0f, iou_loss = 0.0f;
            for (int i = 0; i < Sn * Bn; i++) { hm_loss += sterm_hm[i]; iou_loss += sterm_iou[i]; }
            hm_loss *= (1.0f / (float)(Sn * Bn));
            iou_loss *= (1.0f / (float)(Sn * Bn));
            float loss = 1.0f * hm_loss + 0.1f * iou_loss;
            out[0] = loss;
            if (out_size > 1) out[1] = hm_loss;
            if (out_size > 2) out[2] = iou_loss;
        }
    }
}

// ============================================================================
extern "C" void kernel_launch(void* const* d_in, const int* in_sizes, int n_in,
                              void* d_out, int out_size)
{
    const float* hm      = (const float*)d_in[0];
    const float* wh_map  = (const float*)d_in[1];
    const float* reg_map = (const float*)d_in[2];
    const float* reg_gt  = (const float*)d_in[3];
    const float* wh_gt   = (const float*)d_in[4];
    const int*   ind     = (const int*)d_in[5];
    const int*   ctr     = (const int*)d_in[6];
    const int*   mask    = (const int*)d_in[7];
    float* out = (float*)d_out;

    dim3 grid(Hd, Bn);
    passAB_kernel<<<grid, 128>>>(hm, ctr, mask);
    passC_kernel<<<TOT_BLOCKS, 256>>>(wh_map, reg_map, reg_gt, wh_gt, ind, mask, out, out_size);
}

// round 16
// speedup vs baseline: 1.1384x; 1.0838x over previous
#include <cuda_runtime.h>
#include <cstdint>

#define Sn 2
#define Bn 16
#define Kn 128
#define Hd 128
#define Wd 128
#define HWn (Hd*Wd)

#define EPSf 1e-6f
#define MAXD 181.01933598375618f
#define MAXD2 32768.0f
#define MPD (MAXD + EPSf)

#define C1_BLOCKS 512
#define IOU_BLOCKS 32
#define TOT_BLOCKS (C1_BLOCKS + IOU_BLOCKS)

typedef unsigned long long ull;

// ---- device scratch ----
static __device__ float4 g_t1[Bn * Hd];                 // per (b,row)
static __device__ float  g_part2[Bn * Kn * Hd * 2];     // ((b*Kn+slot)*Hd + row)*2 + s
static __device__ float  g_minn[Sn * Bn * Kn];
static __device__ float  g_iou[Sn * Bn];
static __device__ int    g_msum[Bn];
static __device__ int    g_done;

__device__ __forceinline__ float sqrt_ap(float x) {
    float r; asm("sqrt.approx.f32 %0, %1;" : "=f"(r) : "f"(x)); return r;
}
__device__ __forceinline__ float rcp_ap(float x) {
    float r; asm("rcp.approx.f32 %0, %1;" : "=f"(r) : "f"(x)); return r;
}
__device__ __forceinline__ ull pk(float lo, float hi) {
    ull r; asm("mov.b64 %0, {%1, %2};" : "=l"(r) : "f"(lo), "f"(hi)); return r;
}
__device__ __forceinline__ void upk(float& lo, float& hi, ull v) {
    asm("mov.b64 {%0, %1}, %2;" : "=f"(lo), "=f"(hi) : "l"(v));
}
__device__ __forceinline__ ull mul2(ull a, ull b) {
    ull r; asm("mul.rn.f32x2 %0, %1, %2;" : "=l"(r) : "l"(a), "l"(b)); return r;
}
__device__ __forceinline__ ull fma2(ull a, ull b, ull c) {
    ull r; asm("fma.rn.f32x2 %0, %1, %2, %3;" : "=l"(r) : "l"(a), "l"(b), "l"(c)); return r;
}
__device__ __forceinline__ float smoothl(float l) {
    return (l < 0.2f) ? (2.5f * l * l) : (l - 0.1f);
}

// ============================================================================
// Kernel 1 — fused pass AB: sigmoid + compaction; term1 (dmin) + term2 partials
// grid: (row=128, b=16), block: 128 threads
// ============================================================================
__global__ void __launch_bounds__(128) passAB_kernel(
    const float* __restrict__ hm, const int* __restrict__ ctr,
    const int* __restrict__ mask)
{
    const int row = blockIdx.x, b = blockIdx.y;
    const int tid = threadIdx.x;
    const int wid = tid >> 5, lid = tid & 31;

    __shared__ float4 spq[Wd];
    __shared__ float  spx[Kn], sdy2[Kn];
    __shared__ int    wcnt[4];
    __shared__ float  red[4][4];
    __shared__ ull    shalf1[Kn];          // half-1 partial per slot

    const float fy = (float)row, fx = (float)tid;

    // --- sigmoid for this row's cells (both s) ---
    const int base = b * HWn + row * Wd + tid;
    float h0 = hm[base];
    float h1 = hm[Bn * HWn + base];
    float p0 = 1.0f / (1.0f + __expf(-h0));
    float p1 = 1.0f / (1.0f + __expf(-h1));
    p0 = fminf(fmaxf(p0, 1e-4f), 1.0f - 1e-4f);
    p1 = fminf(fmaxf(p1, 1e-4f), 1.0f - 1e-4f);
    spq[tid] = make_float4(p0, p1, MPD - p0 * MAXD, MPD - p1 * MAXD);

    // --- compaction of valid points (thread = k) ---
    const int mk = mask[b * Kn + tid];
    unsigned bal = __ballot_sync(0xFFFFFFFFu, mk != 0);
    if (lid == 0) wcnt[wid] = __popc(bal);
    __syncthreads();
    int off = 0;
#pragma unroll
    for (int i = 0; i < 4; i++) if (i < wid) off += wcnt[i];
    const int V = wcnt[0] + wcnt[1] + wcnt[2] + wcnt[3];
    if (mk) {
        int slot = off + __popc(bal & ((1u << lid) - 1u));
        float pxk = (float)ctr[(b * Kn + tid) * 2 + 0];
        float pyk = (float)ctr[(b * Kn + tid) * 2 + 1];
        spx[slot] = pxk;
        float dyv = fy - pyk;
        sdy2[slot] = dyv * dyv;
    }
    __syncthreads();

    // ---- term1: dmin per cell + row reduce ----
    float mind = MAXD2;
#pragma unroll 4
    for (int j = 0; j < V; j++) {
        float dxv = fx - spx[j];
        mind = fminf(mind, fmaf(dxv, dxv, sdy2[j]));
    }
    float dmin = sqrt_ap(mind);

    float v0 = p0 * dmin, v1 = p1 * dmin, v2 = p0, v3 = p1;
#pragma unroll
    for (int o = 16; o > 0; o >>= 1) {
        v0 += __shfl_down_sync(0xFFFFFFFFu, v0, o);
        v1 += __shfl_down_sync(0xFFFFFFFFu, v1, o);
        v2 += __shfl_down_sync(0xFFFFFFFFu, v2, o);
        v3 += __shfl_down_sync(0xFFFFFFFFu, v3, o);
    }
    if (lid == 0) { red[wid][0] = v0; red[wid][1] = v1; red[wid][2] = v2; red[wid][3] = v3; }
    __syncthreads();
    if (tid == 0) {
        float4 o4;
        o4.x = red[0][0] + red[1][0] + red[2][0] + red[3][0];
        o4.y = red[0][1] + red[1][1] + red[2][1] + red[3][1];
        o4.z = red[0][2] + red[1][2] + red[2][2] + red[3][2];
        o4.w = red[0][3] + red[1][3] + red[2][3] + red[3][3];
        g_t1[b * Hd + row] = o4;
    }

    // ---- term2: item = (slot, half); half = (w >= V) so warps share half ----
    ull acc0reg = 0ULL;
    for (int w = tid; w < 2 * V; w += 128) {
        const int half = (w >= V) ? 1 : 0;
        const int slot = w - (half ? V : 0);
        const float px = spx[slot];
        const float dy2 = sdy2[slot];
        const int xb = half << 6;
        const float u0 = (float)xb - px;
        ull acc = 0ULL;
#pragma unroll 4
        for (int g = 0; g < 16; g++) {
            const float ug = u0 + (float)(g * 4);
            float P[4]; ull xv[4];
#pragma unroll
            for (int j = 0; j < 4; j++) {
                float t = ug + (float)j;
                float dsq = fmaf(t, t, dy2);
                float d = sqrt_ap(dsq);
                float4 pq = spq[xb + g * 4 + j];       // warp-uniform -> LDS broadcast
                float x0 = fmaf(pq.x, d, pq.z);        // (1-p)M + p d + eps
                float x1 = fmaf(pq.y, d, pq.w);
                xv[j] = pk(x0, x1);
                P[j] = x0 * x1;
            }
            // one rcp for 8 values
            float P01 = P[0] * P[1];
            float P23 = P[2] * P[3];
            float r = rcp_ap(P01 * P23);
            float r01 = r * P23;
            float r23 = r * P01;
            float qv[4];
            qv[0] = r01 * P[1];
            qv[1] = r01 * P[0];
            qv[2] = r23 * P[3];
            qv[3] = r23 * P[2];
#pragma unroll
            for (int j = 0; j < 4; j++) {
                float x0, x1; upk(x0, x1, xv[j]);
                float i0 = qv[j] * x1;
                float i1 = qv[j] * x0;
                ull iv = pk(i0, i1);
                ull a = mul2(iv, iv);
                a = mul2(a, a);
                a = mul2(a, a);
                acc = fma2(a, iv, acc);                // += x^-9
            }
        }
        if (half) shalf1[slot] = acc;
        else      acc0reg = acc;
    }
    __syncthreads();

    // ---- combine halves per slot; one coalesced float2 store per valid slot ----
    if (tid < V) {
        float a0, a1, b0h, b1h;
        upk(a0, a1, acc0reg);
        upk(b0h, b1h, shalf1[tid]);
        *(float2*)&g_part2[((b * Kn + tid) * Hd + row) * 2] =
            make_float2(a0 + b0h, a1 + b1h);
    }
}

// ============================================================================
// Kernel 2 — fused C1 reduction + IoU + (last block) finalize
// grid: 544 blocks x 256 threads
// ============================================================================
__global__ void __launch_bounds__(256) passC_kernel(
    const float* __restrict__ wh_map, const float* __restrict__ reg_map,
    const float* __restrict__ reg_gt, const float* __restrict__ wh_gt,
    const int* __restrict__ ind, const int* __restrict__ mask,
    float* __restrict__ out, int out_size)
{
    const int bid = blockIdx.x;
    const int tid = threadIdx.x;
    const int warpid = tid >> 5, lane = tid & 31;

    __shared__ int   wcnt[4];
    __shared__ float wred[4];
    __shared__ int   wv[4];
    __shared__ int   slast;

    if (bid < C1_BLOCKS) {
        // ---- C1: reduce over 128 rows ----
        const int sb = bid >> 4;                 // 0..31
        const int s = sb >> 4, b = sb & (Bn - 1);
        const int slot = ((bid & 15) << 3) + warpid;

        if (tid < Kn) {
            int mk = mask[b * Kn + tid];
            unsigned balm = __ballot_sync(0xFFFFFFFFu, mk != 0);
            if ((tid & 31) == 0) wcnt[tid >> 5] = __popc(balm);
        }
        __syncthreads();
        const int V = wcnt[0] + wcnt[1] + wcnt[2] + wcnt[3];

        float v = 0.0f;
        if (slot < V) {
            const float* bp = &g_part2[((b * Kn + slot) * Hd) * 2 + s];
            float ssum = 0.0f;
#pragma unroll
            for (int t = 0; t < 4; t++) ssum += bp[(lane + t * 32) * 2];
#pragma unroll
            for (int o = 16; o > 0; o >>= 1) ssum += __shfl_down_sync(0xFFFFFFFFu, ssum, o);
            if (lane == 0)
                v = powf(ssum * (1.0f / (float)HWn), -1.0f / 9.0f);
        }
        if (lane == 0) g_minn[sb * Kn + slot] = v;
    } else {
        // ---- IoU: per (s,b), thread = k (first 128 threads) ----
        const int sb = bid - C1_BLOCKS;
        const int b = sb & (Bn - 1);
        if (tid < Kn) {
            const int k = tid;
            const int mk = mask[b * Kn + k];
            unsigned balm = __ballot_sync(0xFFFFFFFFu, mk != 0);
            float v = 0.0f;
            if (mk) {
                int id = ind[b * Kn + k];
                float R0 = reg_map[(sb * 2 + 0) * HWn + id];
                float R1 = reg_map[(sb * 2 + 1) * HWn + id];
                float W0 = wh_map[(sb * 2 + 0) * HWn + id];
                float W1 = wh_map[(sb * 2 + 1) * HWn + id];
                float g0 = reg_gt[(b * Kn + k) * 2 + 0];
                float g1 = reg_gt[(b * Kn + k) * 2 + 1];
                float wg = wh_gt[(b * Kn + k) * 2 + 0];
                float hg = wh_gt[(b * Kn + k) * 2 + 1];
                float adx = fabsf(g0 - R0);
                float ady = fabsf(g1 - R1);
                float ldx = 1.0f - fmaxf((wg - 2.0f * adx) / (wg + 2.0f * adx + EPSf), 0.0f);
                float ldy = 1.0f - fmaxf((hg - 2.0f * ady) / (hg + 2.0f * ady + EPSf), 0.0f);
                float ldw = 1.0f - fminf(wg / (W0 + EPSf), W0 / (wg + EPSf));
                float ldh = 1.0f - fminf(hg / (W1 + EPSf), W1 / (hg + EPSf));
                v = smoothl(ldx) + smoothl(ldy) + smoothl(ldw) + smoothl(ldh);
            }
#pragma unroll
            for (int o = 16; o > 0; o >>= 1) v += __shfl_down_sync(0xFFFFFFFFu, v, o);
            if ((tid & 31) == 0) { wred[tid >> 5] = v; wv[tid >> 5] = __popc(balm); }
        }
        __syncthreads();
        if (tid == 0) {
            g_iou[sb] = wred[0] + wred[1] + wred[2] + wred[3];
            if (sb < Bn) g_msum[sb] = wv[0] + wv[1] + wv[2] + wv[3];
        }
    }

    // ---- completion protocol ----
    __threadfence();
    __syncthreads();
    if (tid == 0) {
        int prev = atomicAdd(&g_done, 1);
        slast = (prev == TOT_BLOCKS - 1) ? 1 : 0;
        if (slast) g_done = 0;
    }
    __syncthreads();

    if (slast) {
        __threadfence();
        __shared__ float sterm_hm[Sn * Bn], sterm_iou[Sn * Bn];
        for (int sb2 = warpid; sb2 < Sn * Bn; sb2 += 8) {
            const int b = sb2 & (Bn - 1);
            const int s = sb2 >> 4;
            float t2s = 0.0f, num = 0.0f, den = 0.0f;
#pragma unroll
            for (int t = 0; t < 4; t++) {
                t2s += g_minn[sb2 * Kn + lane + t * 32];
                float4 v = g_t1[b * Hd + lane + t * 32];
                num += (s == 0) ? v.x : v.y;
                den += (s == 0) ? v.z : v.w;
            }
#pragma unroll
            for (int o = 16; o > 0; o >>= 1) {
                t2s += __shfl_down_sync(0xFFFFFFFFu, t2s, o);
                num += __shfl_down_sync(0xFFFFFFFFu, num, o);
                den += __shfl_down_sync(0xFFFFFFFFu, den, o);
            }
            if (lane == 0) {
                int ms = g_msum[b];
                float validb = (ms > 0) ? 1.0f : 0.0f;
                float fm = fmaxf((float)ms, 1.0f);
                float t1 = num / (den + EPSf);
                sterm_hm[sb2] = (t1 + t2s / fm) * validb;
                sterm_iou[sb2] = (g_iou[sb2] / (fm * 4.0f)) * validb;
            }
        }
        __syncthreads();
        if (tid == 0) {
            float hm_loss = 0.0f, iou_loss = 0.0f;
            for (int i = 0; i < Sn * Bn; i++) { hm_loss += sterm_hm[i]; iou_loss += sterm_iou[i]; }
            hm_loss *= (1.0f / (float)(Sn * Bn));
            iou_loss *= (1.0f / (float)(Sn * Bn));
            float loss = 1.0f * hm_loss + 0.1f * iou_loss;
            out[0] = loss;
            if (out_size > 1) out[1] = hm_loss;
            if (out_size > 2) out[2] = iou_loss;
        }
    }
}

// ============================================================================
extern "C" void kernel_launch(void* const* d_in, const int* in_sizes, int n_in,
                              void* d_out, int out_size)
{
    const float* hm      = (const float*)d_in[0];
    const float* wh_map  = (const float*)d_in[1];
    const float* reg_map = (const float*)d_in[2];
    const float* reg_gt  = (const float*)d_in[3];
    const float* wh_gt   = (const float*)d_in[4];
    const int*   ind     = (const int*)d_in[5];
    const int*   ctr     = (const int*)d_in[6];
    const int*   mask    = (const int*)d_in[7];
    float* out = (float*)d_out;

    dim3 grid(Hd, Bn);
    passAB_kernel<<<grid, 128>>>(hm, ctr, mask);
    passC_kernel<<<TOT_BLOCKS, 256>>>(wh_map, reg_map, reg_gt, wh_gt, ind, mask, out, out_size);
}